// round 6
// baseline (speedup 1.0000x reference)
#include <cuda_runtime.h>
#include <cuda_bf16.h>

// Problem constants (fixed by the reference: B=4096, N=256, K=16)
#define NN   256
#define KK   16
#define PP   32640           // N*(N-1)/2
#define BB   4096
#define TPB  256             // threads per block
#define EPB  8               // pairs handled per thread (tile = TPB*EPB = 2048 pairs)
#define GX   16              // p-tiles: 16*2048 = 32768 >= 32640
#define GY   128             // batch stripes: each block loops 4096/128 = 32 rows

// pstart(i) = number of pairs before row i = i*(N-1) - i*(i-1)/2
__device__ __forceinline__ int pstart(int i) {
    return i * (NN - 1) - (i * (i - 1)) / 2;
}

__global__ void __launch_bounds__(TPB)
cross_utpm_kernel(const float* __restrict__ x,
                  const float* __restrict__ L,
                  float* __restrict__ out)
{
    __shared__ float xs[NN];

    const int t  = threadIdx.x;
    const int p0 = blockIdx.x * (TPB * EPB);

    // ---- one-time per-thread setup: pair indices + Gram values (b-invariant) ----
    int   idx_i[EPB];
    int   idx_j[EPB];
    float sp[EPB];
    bool  valid[EPB];

#pragma unroll
    for (int e = 0; e < EPB; e++) {
        int p = p0 + e * TPB + t;            // consecutive threads -> consecutive p
        valid[e] = (p < PP);
        int pc = valid[e] ? p : 0;

        // invert triangular index: i = floor((2N-1 - sqrt((2N-1)^2 - 8p))/2), then fix up
        float disc = 2.0f * NN - 1.0f;       // 511
        int i = (int)floorf((disc - sqrtf(disc * disc - 8.0f * (float)pc)) * 0.5f);
        if (i < 0) i = 0;
        if (i > NN - 2) i = NN - 2;
        while (i < NN - 2 && pstart(i + 1) <= pc) i++;
        while (i > 0 && pstart(i) > pc) i--;

        int j = i + 1 + (pc - pstart(i));
        idx_i[e] = i;
        idx_j[e] = j;

        // sp = L[i,:] . L[j,:]   (K = 16, L is tiny and L2-resident)
        float s = 0.0f;
#pragma unroll
        for (int k = 0; k < KK; k++)
            s += L[i * KK + k] * L[j * KK + k];
        sp[e] = s;
    }

    // ---- main loop over batch rows (strided by GY) ----
    for (int b = blockIdx.y; b < BB; b += GY) {
        __syncthreads();                      // protect xs against previous iteration's readers
        xs[t] = x[(size_t)b * NN + t];        // coalesced 1KB row stage
        __syncthreads();

        float* op = out + (size_t)b * PP + p0 + t;
#pragma unroll
        for (int e = 0; e < EPB; e++) {
            if (valid[e])
                op[e * TPB] = xs[idx_i[e]] * xs[idx_j[e]] * sp[e];
        }
    }
}

extern "C" void kernel_launch(void* const* d_in, const int* in_sizes, int n_in,
                              void* d_out, int out_size)
{
    const float* x = (const float*)d_in[0];        // [4096, 256]
    const float* L = (const float*)d_in[1];        // [256, 16]
    float* out     = (float*)d_out;                // [4096, 32640]

    dim3 grid(GX, GY);
    cross_utpm_kernel<<<grid, TPB>>>(x, L, out);
}

// round 7
// speedup vs baseline: 1.0005x; 1.0005x over previous
#include <cuda_runtime.h>
#include <cuda_bf16.h>

// Problem constants (fixed by the reference: B=4096, N=256, K=16)
#define NN   256
#define KK   16
#define PP   32640           // N*(N-1)/2
#define BB   4096
#define TPB  256             // threads per block
#define EPB  8               // pairs handled per thread (tile = TPB*EPB = 2048 pairs)
#define GX   16              // p-tiles: 16*2048 = 32768 >= 32640
#define GY   128             // batch stripes: each block loops 4096/128 = 32 rows

// pstart(i) = number of pairs before row i = i*(N-1) - i*(i-1)/2
__device__ __forceinline__ int pstart(int i) {
    return i * (NN - 1) - (i * (i - 1)) / 2;
}

__global__ void __launch_bounds__(TPB)
cross_utpm_kernel(const float* __restrict__ x,
                  const float* __restrict__ L,
                  float* __restrict__ out)
{
    __shared__ float xs[NN];

    const int t  = threadIdx.x;
    const int p0 = blockIdx.x * (TPB * EPB);

    // ---- one-time per-thread setup: pair indices + Gram values (b-invariant) ----
    int   idx_i[EPB];
    int   idx_j[EPB];
    float sp[EPB];
    bool  valid[EPB];

#pragma unroll
    for (int e = 0; e < EPB; e++) {
        int p = p0 + e * TPB + t;            // consecutive threads -> consecutive p
        valid[e] = (p < PP);
        int pc = valid[e] ? p : 0;

        // invert triangular index: i = floor((2N-1 - sqrt((2N-1)^2 - 8p))/2), then fix up
        float disc = 2.0f * NN - 1.0f;       // 511
        int i = (int)floorf((disc - sqrtf(disc * disc - 8.0f * (float)pc)) * 0.5f);
        if (i < 0) i = 0;
        if (i > NN - 2) i = NN - 2;
        while (i < NN - 2 && pstart(i + 1) <= pc) i++;
        while (i > 0 && pstart(i) > pc) i--;

        int j = i + 1 + (pc - pstart(i));
        idx_i[e] = i;
        idx_j[e] = j;

        // sp = L[i,:] . L[j,:]   (K = 16, L is tiny and L2-resident)
        float s = 0.0f;
#pragma unroll
        for (int k = 0; k < KK; k++)
            s += L[i * KK + k] * L[j * KK + k];
        sp[e] = s;
    }

    // ---- main loop over batch rows (strided by GY) ----
    for (int b = blockIdx.y; b < BB; b += GY) {
        __syncthreads();                      // protect xs against previous iteration's readers
        xs[t] = x[(size_t)b * NN + t];        // coalesced 1KB row stage
        __syncthreads();

        float* op = out + (size_t)b * PP + p0 + t;
#pragma unroll
        for (int e = 0; e < EPB; e++) {
            if (valid[e])
                op[e * TPB] = xs[idx_i[e]] * xs[idx_j[e]] * sp[e];
        }
    }
}

extern "C" void kernel_launch(void* const* d_in, const int* in_sizes, int n_in,
                              void* d_out, int out_size)
{
    const float* x = (const float*)d_in[0];        // [4096, 256]
    const float* L = (const float*)d_in[1];        // [256, 16]
    float* out     = (float*)d_out;                // [4096, 32640]

    dim3 grid(GX, GY);
    cross_utpm_kernel<<<grid, TPB>>>(x, L, out);
}

// round 8
// speedup vs baseline: 1.0021x; 1.0016x over previous
#include <cuda_runtime.h>
#include <cuda_bf16.h>

// Problem constants (fixed by the reference: B=4096, N=256, K=16)
#define NN   256
#define KK   16
#define PP   32640           // N*(N-1)/2
#define BB   4096
#define TPB  256             // threads per block
#define EPB  8               // pairs handled per thread (tile = TPB*EPB = 2048 pairs)
#define GX   16              // p-tiles: 16*2048 = 32768 >= 32640
#define GY   128             // batch stripes: each block loops 4096/128 = 32 rows

// pstart(i) = number of pairs before row i = i*(N-1) - i*(i-1)/2
__device__ __forceinline__ int pstart(int i) {
    return i * (NN - 1) - (i * (i - 1)) / 2;
}

__global__ void __launch_bounds__(TPB)
cross_utpm_kernel(const float* __restrict__ x,
                  const float* __restrict__ L,
                  float* __restrict__ out)
{
    __shared__ float xs[NN];

    const int t  = threadIdx.x;
    const int p0 = blockIdx.x * (TPB * EPB);

    // ---- one-time per-thread setup: pair indices + Gram values (b-invariant) ----
    int   idx_i[EPB];
    int   idx_j[EPB];
    float sp[EPB];
    bool  valid[EPB];

#pragma unroll
    for (int e = 0; e < EPB; e++) {
        int p = p0 + e * TPB + t;            // consecutive threads -> consecutive p
        valid[e] = (p < PP);
        int pc = valid[e] ? p : 0;

        // invert triangular index: i = floor((2N-1 - sqrt((2N-1)^2 - 8p))/2), then fix up
        float disc = 2.0f * NN - 1.0f;       // 511
        int i = (int)floorf((disc - sqrtf(disc * disc - 8.0f * (float)pc)) * 0.5f);
        if (i < 0) i = 0;
        if (i > NN - 2) i = NN - 2;
        while (i < NN - 2 && pstart(i + 1) <= pc) i++;
        while (i > 0 && pstart(i) > pc) i--;

        int j = i + 1 + (pc - pstart(i));
        idx_i[e] = i;
        idx_j[e] = j;

        // sp = L[i,:] . L[j,:]   (K = 16, L is tiny and L2-resident)
        float s = 0.0f;
#pragma unroll
        for (int k = 0; k < KK; k++)
            s += L[i * KK + k] * L[j * KK + k];
        sp[e] = s;
    }

    // ---- main loop over batch rows (strided by GY) ----
    for (int b = blockIdx.y; b < BB; b += GY) {
        __syncthreads();                      // protect xs against previous iteration's readers
        xs[t] = x[(size_t)b * NN + t];        // coalesced 1KB row stage
        __syncthreads();

        float* op = out + (size_t)b * PP + p0 + t;
#pragma unroll
        for (int e = 0; e < EPB; e++) {
            if (valid[e])
                op[e * TPB] = xs[idx_i[e]] * xs[idx_j[e]] * sp[e];
        }
    }
}

extern "C" void kernel_launch(void* const* d_in, const int* in_sizes, int n_in,
                              void* d_out, int out_size)
{
    const float* x = (const float*)d_in[0];        // [4096, 256]
    const float* L = (const float*)d_in[1];        // [256, 16]
    float* out     = (float*)d_out;                // [4096, 32640]

    dim3 grid(GX, GY);
    cross_utpm_kernel<<<grid, TPB>>>(x, L, out);
}